// round 7
// baseline (speedup 1.0000x reference)
#include <cuda_runtime.h>
#include <cuda_bf16.h>
#include <math.h>
#include <stdint.h>

#define B_SZ   16384
#define NTAB   26
#define VOCAB  100000
#define EMB_D  64

// ======================= scratch (device globals) ==========================
__device__ __align__(256) float g_x [B_SZ * 64];            // bot MLP out fp32
__device__ __align__(256) float g_z2[B_SZ * 256];           // top L1 out fp32

__device__ __align__(256) __nv_bfloat16 g_x1h[B_SZ * 512];
__device__ __align__(256) __nv_bfloat16 g_x1l[B_SZ * 512];
__device__ __align__(256) __nv_bfloat16 g_x2h[B_SZ * 256];
__device__ __align__(256) __nv_bfloat16 g_x2l[B_SZ * 256];
__device__ __align__(256) __nv_bfloat16 g_Rh [B_SZ * 448];
__device__ __align__(256) __nv_bfloat16 g_Rl [B_SZ * 448];
__device__ __align__(256) __nv_bfloat16 g_z1h[B_SZ * 512];
__device__ __align__(256) __nv_bfloat16 g_z1l[B_SZ * 512];

__device__ __align__(256) __nv_bfloat16 g_bW1h[256 * 512];
__device__ __align__(256) __nv_bfloat16 g_bW1l[256 * 512];
__device__ __align__(256) __nv_bfloat16 g_bW2h[64 * 256];
__device__ __align__(256) __nv_bfloat16 g_bW2l[64 * 256];
__device__ __align__(256) __nv_bfloat16 g_tW0h[512 * 448];
__device__ __align__(256) __nv_bfloat16 g_tW0l[512 * 448];
__device__ __align__(256) __nv_bfloat16 g_tW1h[256 * 512];
__device__ __align__(256) __nv_bfloat16 g_tW1l[256 * 512];

__device__ int g_idx_is64;

// ======================= helpers ============================================
__device__ __forceinline__ uint32_t smem_u32(const void* p) {
    uint32_t a;
    asm("{ .reg .u64 t; cvta.to.shared.u64 t, %1; cvt.u32.u64 %0, t; }"
        : "=r"(a) : "l"(p));
    return a;
}
__device__ __forceinline__ void cpa16(uint32_t saddr, const void* g) {
    asm volatile("cp.async.cg.shared.global [%0], [%1], 16;" :: "r"(saddr), "l"(g));
}
__device__ __forceinline__ void cpa_commit() {
    asm volatile("cp.async.commit_group;" ::: "memory");
}
__device__ __forceinline__ void cpa_wait1() {
    asm volatile("cp.async.wait_group 1;" ::: "memory");
}
__device__ __forceinline__ void cpa_wait0() {
    asm volatile("cp.async.wait_group 0;" ::: "memory");
}
__device__ __forceinline__ void ldm_x4(uint32_t a, uint32_t& r0, uint32_t& r1,
                                       uint32_t& r2, uint32_t& r3) {
    asm volatile("ldmatrix.sync.aligned.m8n8.x4.shared.b16 {%0,%1,%2,%3}, [%4];"
                 : "=r"(r0), "=r"(r1), "=r"(r2), "=r"(r3) : "r"(a));
}
__device__ __forceinline__ void mma16816(float* c, const uint32_t* a,
                                         const uint32_t* b) {
    asm volatile(
        "mma.sync.aligned.m16n8k16.row.col.f32.bf16.bf16.f32 "
        "{%0,%1,%2,%3}, {%4,%5,%6,%7}, {%8,%9}, {%0,%1,%2,%3};"
        : "+f"(c[0]), "+f"(c[1]), "+f"(c[2]), "+f"(c[3])
        : "r"(a[0]), "r"(a[1]), "r"(a[2]), "r"(a[3]), "r"(b[0]), "r"(b[1]));
}
__device__ __forceinline__ void split_f32(float v, __nv_bfloat16& h, __nv_bfloat16& l) {
    h = __float2bfloat16(v);
    l = __float2bfloat16(v - __bfloat162float(h));
}

// =========== fused prep: detect idx dtype + pad/split all 4 weights ========
__device__ __forceinline__ void padsplit_one(const float* W, __nv_bfloat16* Wh,
                                             __nv_bfloat16* Wl, int i,
                                             int Kin, int Kpad) {
    const int n = i / Kpad;
    const int k = i - n * Kpad;
    const float v = (k < Kin) ? W[n * Kin + k] : 0.f;
    __nv_bfloat16 h, l; split_f32(v, h, l);
    Wh[i] = h; Wl[i] = l;
}

__global__ void __launch_bounds__(256) prep_kernel(
    const float* __restrict__ bW1, const float* __restrict__ bW2,
    const float* __restrict__ tW0, const float* __restrict__ tW1,
    const int* __restrict__ lsi32,
    __nv_bfloat16* __restrict__ bW1h, __nv_bfloat16* __restrict__ bW1l,
    __nv_bfloat16* __restrict__ bW2h, __nv_bfloat16* __restrict__ bW2l,
    __nv_bfloat16* __restrict__ tW0h, __nv_bfloat16* __restrict__ tW0l,
    __nv_bfloat16* __restrict__ tW1h, __nv_bfloat16* __restrict__ tW1l)
{
    const int bid = blockIdx.x;
    if (bid == 1984) {
        // index dtype detect (warp 0 only)
        if (threadIdx.x < 32) {
            int any = 0;
            for (int k = threadIdx.x; k < 2048; k += 32)
                if (lsi32[2 * k + 1] != 0) any = 1;
            any = __any_sync(0xFFFFFFFFu, any);
            if (threadIdx.x == 0) g_idx_is64 = any ? 0 : 1;
        }
        return;
    }
    const int i = bid * 256 + threadIdx.x;
    if (i < 131072) {
        padsplit_one(bW1, bW1h, bW1l, i, 512, 512);                 // 256x512
    } else if (i < 147456) {
        padsplit_one(bW2, bW2h, bW2l, i - 131072, 256, 256);        // 64x256
    } else if (i < 376832) {
        padsplit_one(tW0, tW0h, tW0l, i - 147456, 415, 448);        // 512x448
    } else {
        padsplit_one(tW1, tW1h, tW1l, i - 376832, 512, 512);        // 256x512
    }
}

// ======================= bot layer 0 (K=13) -> split out ====================
__global__ void __launch_bounds__(256) bot0_kernel(
    const float* __restrict__ X, const float* __restrict__ W,
    const float* __restrict__ bias,
    __nv_bfloat16* __restrict__ Yh, __nv_bfloat16* __restrict__ Yl)
{
    __shared__ float sW[512 * 13];
    __shared__ float sb[512];
    __shared__ float sx[16 * 13];
    const int tid = threadIdx.x;
    const int r0 = blockIdx.x * 16;
    for (int i = tid; i < 512 * 13; i += 256) sW[i] = W[i];
    for (int i = tid; i < 512; i += 256) sb[i] = bias[i];
    for (int i = tid; i < 16 * 13; i += 256) sx[i] = X[r0 * 13 + i];
    __syncthreads();
    for (int o = tid; o < 16 * 512; o += 256) {
        const int r = o >> 9;
        const int c = o & 511;
        float acc = sb[c];
        #pragma unroll
        for (int k = 0; k < 13; k++) acc += sx[r * 13 + k] * sW[c * 13 + k];
        acc = fmaxf(acc, 0.f);
        __nv_bfloat16 h, l; split_f32(acc, h, l);
        const size_t idx = (size_t)(r0 + r) * 512 + c;
        Yh[idx] = h; Yl[idx] = l;
    }
}

// ======================= mma.sync bf16x3 GEMM (templated N tile) ============
// C[M,N] = act(A[M,K] @ W[N,K]^T + bias). A/W pre-split hi/lo bf16.
// CTA tile 128 x NT, BK=64 bf16 (128B rows, XOR swizzle), double-buffered
// cp.async. 8 warps in 4(M) x 2(N); each warp 32 x NT/2 via m16n8k16.
__device__ __forceinline__ uint32_t swz(int row, int chunk) {
    return (uint32_t)(row * 128 + ((chunk ^ (row & 7)) * 16));
}

template<int NT>
__global__ void __launch_bounds__(256) gemm_mma(
    const __nv_bfloat16* __restrict__ Ah, const __nv_bfloat16* __restrict__ Al,
    const __nv_bfloat16* __restrict__ Wh, const __nv_bfloat16* __restrict__ Wl,
    const float* __restrict__ bias, int K, int NC,
    float* __restrict__ Cf,
    __nv_bfloat16* __restrict__ Ch, __nv_bfloat16* __restrict__ Cl,
    int ldc, int relu, int splitOut)
{
    constexpr uint32_t STAGE = 32768u + 2u * NT * 128u;
    constexpr int WCOL = NT / 2;          // cols per warp
    constexpr int NP   = NT / 32;         // B ldmatrix.x4 loads per half
    constexpr int NU   = NT / 16;         // n8-pairs (mma B frags) per warp

    extern __shared__ char smem[];
    const uint32_t sb = smem_u32(smem);
    const int tid  = threadIdx.x;
    const int lane = tid & 31;
    const int wid  = tid >> 5;
    const int wm   = wid >> 1;
    const int wn   = wid & 1;
    const int m0 = blockIdx.y * 128;
    const int n0 = blockIdx.x * NT;
    const size_t rowB = (size_t)K * 2;

    const char* gAh = (const char*)Ah + (size_t)m0 * rowB;
    const char* gAl = (const char*)Al + (size_t)m0 * rowB;
    const char* gWh = (const char*)Wh + (size_t)n0 * rowB;
    const char* gWl = (const char*)Wl + (size_t)n0 * rowB;

    float acc[2][NU][4];
    #pragma unroll
    for (int t = 0; t < 2; t++)
        #pragma unroll
        for (int u = 0; u < NU; u++)
            #pragma unroll
            for (int v = 0; v < 4; v++) acc[t][u][v] = 0.f;

    auto load_stage = [&](int c) {
        const uint32_t so = sb + (uint32_t)(c & 1) * STAGE;
        const size_t kb = (size_t)c * 128;
        #pragma unroll
        for (int i = 0; i < 4; i++) {
            const int e = tid + i * 256;
            const int row = e >> 3;
            const int ch  = e & 7;
            const size_t gs = (size_t)row * rowB + kb + ch * 16;
            const uint32_t d = swz(row, ch);
            cpa16(so + d,          gAh + gs);
            cpa16(so + 16384 + d,  gAl + gs);
        }
        #pragma unroll
        for (int i = 0; i < NT / 32; i++) {
            const int e = tid + i * 256;
            const int row = e >> 3;
            const int ch  = e & 7;
            const size_t gs = (size_t)row * rowB + kb + ch * 16;
            const uint32_t d = swz(row, ch);
            cpa16(so + 32768 + d,            gWh + gs);
            cpa16(so + 32768 + NT * 128 + d, gWl + gs);
        }
        cpa_commit();
    };

    load_stage(0);
    for (int c = 0; c < NC; ++c) {
        if (c + 1 < NC) load_stage(c + 1);
        if (c + 1 < NC) cpa_wait1(); else cpa_wait0();
        __syncthreads();

        const uint32_t so = sb + (uint32_t)(c & 1) * STAGE;
        const uint32_t sAhB = so, sAlB = so + 16384;
        const uint32_t sWhB = so + 32768, sWlB = so + 32768 + NT * 128;

        #pragma unroll
        for (int kk = 0; kk < 4; kk++) {
            uint32_t ah[2][4], al[2][4], bh[NP * 4], bl[NP * 4];
            #pragma unroll
            for (int t = 0; t < 2; t++) {
                const int row = wm * 32 + t * 16 + (lane & 15);
                const int ch  = kk * 2 + (lane >> 4);
                const uint32_t d = swz(row, ch);
                ldm_x4(sAhB + d, ah[t][0], ah[t][1], ah[t][2], ah[t][3]);
                ldm_x4(sAlB + d, al[t][0], al[t][1], al[t][2], al[t][3]);
            }
            #pragma unroll
            for (int p = 0; p < NP; p++) {
                const int row = wn * WCOL + p * 16 + ((lane >> 4) & 1) * 8 + (lane & 7);
                const int ch  = kk * 2 + ((lane >> 3) & 1);
                const uint32_t d = swz(row, ch);
                ldm_x4(sWhB + d, bh[p * 4 + 0], bh[p * 4 + 1], bh[p * 4 + 2], bh[p * 4 + 3]);
                ldm_x4(sWlB + d, bl[p * 4 + 0], bl[p * 4 + 1], bl[p * 4 + 2], bl[p * 4 + 3]);
            }
            #pragma unroll
            for (int t = 0; t < 2; t++)
                #pragma unroll
                for (int u = 0; u < NU; u++) {
                    mma16816(acc[t][u], ah[t], &bh[u * 2]);
                    mma16816(acc[t][u], ah[t], &bl[u * 2]);
                    mma16816(acc[t][u], al[t], &bh[u * 2]);
                }
        }
        __syncthreads();
    }

    #pragma unroll
    for (int t = 0; t < 2; t++) {
        const int rbase = m0 + wm * 32 + t * 16 + (lane >> 2);
        #pragma unroll
        for (int u = 0; u < NU; u++) {
            const int gn = n0 + wn * WCOL + u * 8 + (lane & 3) * 2;
            const float b0 = __ldg(&bias[gn]);
            const float b1 = __ldg(&bias[gn + 1]);
            #pragma unroll
            for (int h = 0; h < 2; h++) {
                float v0 = acc[t][u][h * 2 + 0] + b0;
                float v1 = acc[t][u][h * 2 + 1] + b1;
                if (relu) { v0 = fmaxf(v0, 0.f); v1 = fmaxf(v1, 0.f); }
                const size_t idx = (size_t)(rbase + h * 8) * ldc + gn;
                if (splitOut) {
                    __nv_bfloat16 h0, l0, h1, l1;
                    split_f32(v0, h0, l0); split_f32(v1, h1, l1);
                    *reinterpret_cast<__nv_bfloat162*>(Ch + idx) = __halves2bfloat162(h0, h1);
                    *reinterpret_cast<__nv_bfloat162*>(Cl + idx) = __halves2bfloat162(l0, l1);
                } else {
                    *reinterpret_cast<float2*>(Cf + idx) = make_float2(v0, v1);
                }
            }
        }
    }
}

// ======== fused gather + interaction: one block per sample =================
__global__ void __launch_bounds__(128) gather_interact_kernel(
    const float* __restrict__ x, const float* __restrict__ emb,
    const void* __restrict__ lsi,
    __nv_bfloat16* __restrict__ Rh, __nv_bfloat16* __restrict__ Rl)
{
    __shared__ float s[27][65];
    const int b   = blockIdx.x;
    const int tid = threadIdx.x;
    const int wid = tid >> 5;
    const int lane = tid & 31;
    const int is64 = g_idx_is64;
    const long long* ip64 = (const long long*)lsi;
    const int*       ip32 = (const int*)lsi;

    if (tid < 32) {
        float2 v = *reinterpret_cast<const float2*>(x + (size_t)b * 64 + tid * 2);
        s[0][tid * 2] = v.x; s[0][tid * 2 + 1] = v.y;
    }
    for (int t = wid; t < NTAB; t += 4) {
        const size_t base = ((size_t)t * B_SZ + b) * 4;
        float2 acc = make_float2(0.f, 0.f);
        #pragma unroll
        for (int l = 0; l < 4; l++) {
            long long ix = is64 ? ip64[base + l] : (long long)ip32[base + l];
            if (ix < 0) ix = 0;
            if (ix >= VOCAB) ix = VOCAB - 1;
            const float2* row = reinterpret_cast<const float2*>(
                emb + ((size_t)t * VOCAB + (size_t)ix) * EMB_D);
            float2 v = __ldg(&row[lane]);
            acc.x += v.x; acc.y += v.y;
        }
        s[1 + t][lane * 2] = acc.x; s[1 + t][lane * 2 + 1] = acc.y;
    }
    __syncthreads();

    __nv_bfloat16* Rbh = Rh + (size_t)b * 448;
    __nv_bfloat16* Rbl = Rl + (size_t)b * 448;

    if (tid < 64) {
        __nv_bfloat16 h, l; split_f32(s[0][tid], h, l);
        Rbh[tid] = h; Rbl[tid] = l;
    }
    for (int c = 415 + tid; c < 448; c += 128) {
        Rbh[c] = __float2bfloat16(0.f); Rbl[c] = __float2bfloat16(0.f);
    }

    if (tid < 105) {
        int ti = (int)(0.5f * (sqrtf(8.0f * (float)tid + 1.0f) - 1.0f));
        while (ti * (ti + 1) / 2 > tid) --ti;
        while ((ti + 1) * (ti + 2) / 2 <= tid) ++ti;
        const int tj = tid - ti * (ti + 1) / 2;
        const int i0 = 2 * ti, i1 = 2 * ti + 1;
        const int j0 = 2 * tj, j1 = 2 * tj + 1;
        const float* si0 = s[i0];
        const float* si1 = s[(i1 < 27) ? i1 : 26];   // clamp (values unused when OOB)
        const float* sj0 = s[j0];
        const float* sj1 = s[(j1 < 27) ? j1 : 26];   // clamp (values unused when OOB)
        float d00 = 0.f, d01 = 0.f, d10 = 0.f, d11 = 0.f;
        #pragma unroll
        for (int k = 0; k < 64; k++) {
            const float a0 = si0[k], a1 = si1[k];
            const float b0 = sj0[k], b1 = sj1[k];
            d00 += a0 * b0; d01 += a0 * b1;
            d10 += a1 * b0; d11 += a1 * b1;
        }
        __nv_bfloat16 h, l;
        const bool offd = (ti > tj);
        const bool row1 = (i1 < 27);
        if (offd) {
            split_f32(d00, h, l);
            { const int p = i0 * (i0 - 1) / 2 + j0; Rbh[64 + p] = h; Rbl[64 + p] = l; }
            split_f32(d01, h, l);
            { const int p = i0 * (i0 - 1) / 2 + j1; Rbh[64 + p] = h; Rbl[64 + p] = l; }
        }
        if (row1) {
            split_f32(d10, h, l);
            { const int p = i1 * (i1 - 1) / 2 + j0; Rbh[64 + p] = h; Rbl[64 + p] = l; }
            if (offd) {
                split_f32(d11, h, l);
                { const int p = i1 * (i1 - 1) / 2 + j1; Rbh[64 + p] = h; Rbl[64 + p] = l; }
            }
        }
    }
}

// ======================= final layer + sigmoid ==============================
__global__ void __launch_bounds__(256) top_final_kernel(
    const float* __restrict__ Z, const float* __restrict__ W,
    const float* __restrict__ bias, float* __restrict__ out)
{
    const int b = blockIdx.x * 8 + (threadIdx.x >> 5);
    const int lane = threadIdx.x & 31;
    const float* zr = Z + (size_t)b * 256;
    float acc = 0.f;
    #pragma unroll
    for (int k = lane; k < 256; k += 32) acc += zr[k] * W[k];
    #pragma unroll
    for (int off = 16; off > 0; off >>= 1)
        acc += __shfl_xor_sync(0xFFFFFFFFu, acc, off);
    if (lane == 0) {
        const float v = acc + bias[0];
        out[b] = 1.f / (1.f + expf(-v));
    }
}

// ======================= launch =============================================
extern "C" void kernel_launch(void* const* d_in, const int* in_sizes, int n_in,
                              void* d_out, int out_size)
{
    (void)n_in; (void)out_size;
    const float* dense_x = (const float*)d_in[0];
    const void*  lsi     = d_in[2];
    const float* emb     = (const float*)d_in[3];

    const float *bW0, *bb0, *bW1, *bb1, *bW2, *bb2;
    const float *tW0, *tb0, *tW1, *tb1, *tW2, *tb2;
    if (in_sizes[6] == 512 * 415) {
        bW0 = (const float*)d_in[4];  bb0 = (const float*)d_in[5];
        tW0 = (const float*)d_in[6];  tb0 = (const float*)d_in[7];
        bW1 = (const float*)d_in[8];  bb1 = (const float*)d_in[9];
        tW1 = (const float*)d_in[10]; tb1 = (const float*)d_in[11];
        bW2 = (const float*)d_in[12]; bb2 = (const float*)d_in[13];
        tW2 = (const float*)d_in[14]; tb2 = (const float*)d_in[15];
    } else {
        bW0 = (const float*)d_in[4];  bb0 = (const float*)d_in[5];
        bW1 = (const float*)d_in[6];  bb1 = (const float*)d_in[7];
        bW2 = (const float*)d_in[8];  bb2 = (const float*)d_in[9];
        tW0 = (const float*)d_in[10]; tb0 = (const float*)d_in[11];
        tW1 = (const float*)d_in[12]; tb1 = (const float*)d_in[13];
        tW2 = (const float*)d_in[14]; tb2 = (const float*)d_in[15];
    }

    float *x, *z2;
    __nv_bfloat16 *x1h, *x1l, *x2h, *x2l, *Rh, *Rl, *z1h, *z1l;
    __nv_bfloat16 *bW1h, *bW1l, *bW2h, *bW2l, *tW0h, *tW0l, *tW1h, *tW1l;
    cudaGetSymbolAddress((void**)&x,    g_x);
    cudaGetSymbolAddress((void**)&z2,   g_z2);
    cudaGetSymbolAddress((void**)&x1h,  g_x1h);  cudaGetSymbolAddress((void**)&x1l, g_x1l);
    cudaGetSymbolAddress((void**)&x2h,  g_x2h);  cudaGetSymbolAddress((void**)&x2l, g_x2l);
    cudaGetSymbolAddress((void**)&Rh,   g_Rh);   cudaGetSymbolAddress((void**)&Rl,  g_Rl);
    cudaGetSymbolAddress((void**)&z1h,  g_z1h);  cudaGetSymbolAddress((void**)&z1l, g_z1l);
    cudaGetSymbolAddress((void**)&bW1h, g_bW1h); cudaGetSymbolAddress((void**)&bW1l, g_bW1l);
    cudaGetSymbolAddress((void**)&bW2h, g_bW2h); cudaGetSymbolAddress((void**)&bW2l, g_bW2l);
    cudaGetSymbolAddress((void**)&tW0h, g_tW0h); cudaGetSymbolAddress((void**)&tW0l, g_tW0l);
    cudaGetSymbolAddress((void**)&tW1h, g_tW1h); cudaGetSymbolAddress((void**)&tW1l, g_tW1l);

    const int SMEM64  = 2 * (32768 + 2 * 64 * 128);    // 98304
    const int SMEM128 = 2 * (32768 + 2 * 128 * 128);   // 131072
    cudaFuncSetAttribute(gemm_mma<64>,  cudaFuncAttributeMaxDynamicSharedMemorySize, SMEM64);
    cudaFuncSetAttribute(gemm_mma<128>, cudaFuncAttributeMaxDynamicSharedMemorySize, SMEM128);

    // fused prep: detect + all weight pad/splits (launch 0)
    prep_kernel<<<1985, 256>>>(bW1, bW2, tW0, tW1, (const int*)lsi,
                               bW1h, bW1l, bW2h, bW2l, tW0h, tW0l, tW1h, tW1l);

    // bottom MLP -> compact x[B,64]
    bot0_kernel<<<B_SZ / 16, 256>>>(dense_x, bW0, bb0, x1h, x1l);
    gemm_mma<128><<<dim3(2, 128), 256, SMEM128>>>(x1h, x1l, bW1h, bW1l, bb1, 512, 8,
                                                  nullptr, x2h, x2l, 256, 1, 1);
    gemm_mma<64><<<dim3(1, 128), 256, SMEM64>>>(x2h, x2l, bW2h, bW2l, bb2, 256, 4,
                                                x, nullptr, nullptr, 64, 1, 0);

    // fused gather + interaction -> split R[B,448]
    gather_interact_kernel<<<B_SZ, 128>>>(x, emb, lsi, Rh, Rl);

    // top MLP
    gemm_mma<128><<<dim3(4, 128), 256, SMEM128>>>(Rh, Rl, tW0h, tW0l, tb0, 448, 7,
                                                  nullptr, z1h, z1l, 512, 1, 1);
    gemm_mma<128><<<dim3(2, 128), 256, SMEM128>>>(z1h, z1l, tW1h, tW1l, tb1, 512, 8,
                                                  z2, nullptr, nullptr, 256, 1, 0);
    top_final_kernel<<<B_SZ / 8, 256>>>(z2, tW2, tb2, (float*)d_out);
}

// round 8
// speedup vs baseline: 1.0670x; 1.0670x over previous
#include <cuda_runtime.h>
#include <cuda_bf16.h>
#include <math.h>
#include <stdint.h>

#define B_SZ   16384
#define NTAB   26
#define VOCAB  100000
#define EMB_D  64

// ======================= scratch (device globals) ==========================
__device__ __align__(256) float g_x [B_SZ * 64];            // bot MLP out fp32
__device__ __align__(256) float g_z2[B_SZ * 256];           // top L1 out fp32

__device__ __align__(256) __nv_bfloat16 g_x1h[B_SZ * 512];
__device__ __align__(256) __nv_bfloat16 g_x1l[B_SZ * 512];
__device__ __align__(256) __nv_bfloat16 g_x2h[B_SZ * 256];
__device__ __align__(256) __nv_bfloat16 g_x2l[B_SZ * 256];
__device__ __align__(256) __nv_bfloat16 g_Rh [B_SZ * 448];
__device__ __align__(256) __nv_bfloat16 g_Rl [B_SZ * 448];
__device__ __align__(256) __nv_bfloat16 g_z1h[B_SZ * 512];
__device__ __align__(256) __nv_bfloat16 g_z1l[B_SZ * 512];

__device__ __align__(256) __nv_bfloat16 g_bW1h[256 * 512];
__device__ __align__(256) __nv_bfloat16 g_bW1l[256 * 512];
__device__ __align__(256) __nv_bfloat16 g_bW2h[64 * 256];
__device__ __align__(256) __nv_bfloat16 g_bW2l[64 * 256];
__device__ __align__(256) __nv_bfloat16 g_tW0h[512 * 448];
__device__ __align__(256) __nv_bfloat16 g_tW0l[512 * 448];
__device__ __align__(256) __nv_bfloat16 g_tW1h[256 * 512];
__device__ __align__(256) __nv_bfloat16 g_tW1l[256 * 512];

__device__ int g_idx_is64;

// ======================= helpers ============================================
__device__ __forceinline__ uint32_t smem_u32(const void* p) {
    uint32_t a;
    asm("{ .reg .u64 t; cvta.to.shared.u64 t, %1; cvt.u32.u64 %0, t; }"
        : "=r"(a) : "l"(p));
    return a;
}
__device__ __forceinline__ void cpa16(uint32_t saddr, const void* g) {
    asm volatile("cp.async.cg.shared.global [%0], [%1], 16;" :: "r"(saddr), "l"(g));
}
__device__ __forceinline__ void cpa_commit() {
    asm volatile("cp.async.commit_group;" ::: "memory");
}
__device__ __forceinline__ void cpa_wait1() {
    asm volatile("cp.async.wait_group 1;" ::: "memory");
}
__device__ __forceinline__ void cpa_wait0() {
    asm volatile("cp.async.wait_group 0;" ::: "memory");
}
__device__ __forceinline__ void ldm_x4(uint32_t a, uint32_t& r0, uint32_t& r1,
                                       uint32_t& r2, uint32_t& r3) {
    asm volatile("ldmatrix.sync.aligned.m8n8.x4.shared.b16 {%0,%1,%2,%3}, [%4];"
                 : "=r"(r0), "=r"(r1), "=r"(r2), "=r"(r3) : "r"(a));
}
__device__ __forceinline__ void mma16816(float* c, const uint32_t* a,
                                         const uint32_t* b) {
    asm volatile(
        "mma.sync.aligned.m16n8k16.row.col.f32.bf16.bf16.f32 "
        "{%0,%1,%2,%3}, {%4,%5,%6,%7}, {%8,%9}, {%0,%1,%2,%3};"
        : "+f"(c[0]), "+f"(c[1]), "+f"(c[2]), "+f"(c[3])
        : "r"(a[0]), "r"(a[1]), "r"(a[2]), "r"(a[3]), "r"(b[0]), "r"(b[1]));
}
__device__ __forceinline__ void split_f32(float v, __nv_bfloat16& h, __nv_bfloat16& l) {
    h = __float2bfloat16(v);
    l = __float2bfloat16(v - __bfloat162float(h));
}

// =========== fused prep: detect idx dtype + pad/split all 4 weights ========
__device__ __forceinline__ void padsplit_one(const float* W, __nv_bfloat16* Wh,
                                             __nv_bfloat16* Wl, int i,
                                             int Kin, int Kpad) {
    const int n = i / Kpad;
    const int k = i - n * Kpad;
    const float v = (k < Kin) ? W[n * Kin + k] : 0.f;
    __nv_bfloat16 h, l; split_f32(v, h, l);
    Wh[i] = h; Wl[i] = l;
}

__global__ void __launch_bounds__(256) prep_kernel(
    const float* __restrict__ bW1, const float* __restrict__ bW2,
    const float* __restrict__ tW0, const float* __restrict__ tW1,
    const int* __restrict__ lsi32,
    __nv_bfloat16* __restrict__ bW1h, __nv_bfloat16* __restrict__ bW1l,
    __nv_bfloat16* __restrict__ bW2h, __nv_bfloat16* __restrict__ bW2l,
    __nv_bfloat16* __restrict__ tW0h, __nv_bfloat16* __restrict__ tW0l,
    __nv_bfloat16* __restrict__ tW1h, __nv_bfloat16* __restrict__ tW1l)
{
    const int bid = blockIdx.x;
    if (bid == 1984) {
        if (threadIdx.x < 32) {
            int any = 0;
            for (int k = threadIdx.x; k < 2048; k += 32)
                if (lsi32[2 * k + 1] != 0) any = 1;
            any = __any_sync(0xFFFFFFFFu, any);
            if (threadIdx.x == 0) g_idx_is64 = any ? 0 : 1;
        }
        return;
    }
    const int i = bid * 256 + threadIdx.x;
    if (i < 131072) {
        padsplit_one(bW1, bW1h, bW1l, i, 512, 512);                 // 256x512
    } else if (i < 147456) {
        padsplit_one(bW2, bW2h, bW2l, i - 131072, 256, 256);        // 64x256
    } else if (i < 376832) {
        padsplit_one(tW0, tW0h, tW0l, i - 147456, 415, 448);        // 512x448
    } else {
        padsplit_one(tW1, tW1h, tW1l, i - 376832, 512, 512);        // 256x512
    }
}

// ======================= bot layer 0 (K=13) -> split out ====================
__global__ void __launch_bounds__(256) bot0_kernel(
    const float* __restrict__ X, const float* __restrict__ W,
    const float* __restrict__ bias,
    __nv_bfloat16* __restrict__ Yh, __nv_bfloat16* __restrict__ Yl)
{
    __shared__ float sW[512 * 13];
    __shared__ float sb[512];
    __shared__ float sx[16 * 13];
    const int tid = threadIdx.x;
    const int r0 = blockIdx.x * 16;
    for (int i = tid; i < 512 * 13; i += 256) sW[i] = W[i];
    for (int i = tid; i < 512; i += 256) sb[i] = bias[i];
    for (int i = tid; i < 16 * 13; i += 256) sx[i] = X[r0 * 13 + i];
    __syncthreads();
    for (int o = tid; o < 16 * 512; o += 256) {
        const int r = o >> 9;
        const int c = o & 511;
        float acc = sb[c];
        #pragma unroll
        for (int k = 0; k < 13; k++) acc += sx[r * 13 + k] * sW[c * 13 + k];
        acc = fmaxf(acc, 0.f);
        __nv_bfloat16 h, l; split_f32(acc, h, l);
        const size_t idx = (size_t)(r0 + r) * 512 + c;
        Yh[idx] = h; Yl[idx] = l;
    }
}

// ======================= mma.sync bf16x3 GEMM (NT=64, 2 CTA/SM) =============
#define STG 49152u
__device__ __forceinline__ uint32_t swz(int row, int chunk) {
    return (uint32_t)(row * 128 + ((chunk ^ (row & 7)) * 16));
}

__global__ void __launch_bounds__(256) gemm_mma(
    const __nv_bfloat16* __restrict__ Ah, const __nv_bfloat16* __restrict__ Al,
    const __nv_bfloat16* __restrict__ Wh, const __nv_bfloat16* __restrict__ Wl,
    const float* __restrict__ bias, int K, int NC,
    float* __restrict__ Cf,
    __nv_bfloat16* __restrict__ Ch, __nv_bfloat16* __restrict__ Cl,
    int ldc, int relu, int splitOut)
{
    extern __shared__ char smem[];
    const uint32_t sb = smem_u32(smem);
    const int tid  = threadIdx.x;
    const int lane = tid & 31;
    const int wid  = tid >> 5;
    const int wm   = wid >> 1;
    const int wn   = wid & 1;
    const int m0 = blockIdx.y * 128;
    const int n0 = blockIdx.x * 64;
    const size_t rowB = (size_t)K * 2;

    const char* gAh = (const char*)Ah + (size_t)m0 * rowB;
    const char* gAl = (const char*)Al + (size_t)m0 * rowB;
    const char* gWh = (const char*)Wh + (size_t)n0 * rowB;
    const char* gWl = (const char*)Wl + (size_t)n0 * rowB;

    float acc[2][4][4];
    #pragma unroll
    for (int t = 0; t < 2; t++)
        #pragma unroll
        for (int u = 0; u < 4; u++)
            #pragma unroll
            for (int v = 0; v < 4; v++) acc[t][u][v] = 0.f;

    auto load_stage = [&](int c) {
        const uint32_t so = sb + (uint32_t)(c & 1) * STG;
        const size_t kb = (size_t)c * 128;
        #pragma unroll
        for (int i = 0; i < 4; i++) {
            const int e = tid + i * 256;
            const int row = e >> 3;
            const int ch  = e & 7;
            const size_t gs = (size_t)row * rowB + kb + ch * 16;
            const uint32_t d = swz(row, ch);
            cpa16(so + d,          gAh + gs);
            cpa16(so + 16384 + d,  gAl + gs);
        }
        #pragma unroll
        for (int i = 0; i < 2; i++) {
            const int e = tid + i * 256;
            const int row = e >> 3;
            const int ch  = e & 7;
            const size_t gs = (size_t)row * rowB + kb + ch * 16;
            const uint32_t d = swz(row, ch);
            cpa16(so + 32768 + d, gWh + gs);
            cpa16(so + 40960 + d, gWl + gs);
        }
        cpa_commit();
    };

    load_stage(0);
    for (int c = 0; c < NC; ++c) {
        if (c + 1 < NC) load_stage(c + 1);
        if (c + 1 < NC) cpa_wait1(); else cpa_wait0();
        __syncthreads();

        const uint32_t so = sb + (uint32_t)(c & 1) * STG;
        const uint32_t sAhB = so, sAlB = so + 16384;
        const uint32_t sWhB = so + 32768, sWlB = so + 40960;

        #pragma unroll
        for (int kk = 0; kk < 4; kk++) {
            uint32_t ah[2][4], al[2][4], bh[8], bl[8];
            #pragma unroll
            for (int t = 0; t < 2; t++) {
                const int row = wm * 32 + t * 16 + (lane & 15);
                const int ch  = kk * 2 + (lane >> 4);
                const uint32_t d = swz(row, ch);
                ldm_x4(sAhB + d, ah[t][0], ah[t][1], ah[t][2], ah[t][3]);
                ldm_x4(sAlB + d, al[t][0], al[t][1], al[t][2], al[t][3]);
            }
            #pragma unroll
            for (int p = 0; p < 2; p++) {
                const int row = wn * 32 + p * 16 + ((lane >> 4) & 1) * 8 + (lane & 7);
                const int ch  = kk * 2 + ((lane >> 3) & 1);
                const uint32_t d = swz(row, ch);
                ldm_x4(sWhB + d, bh[p * 4 + 0], bh[p * 4 + 1], bh[p * 4 + 2], bh[p * 4 + 3]);
                ldm_x4(sWlB + d, bl[p * 4 + 0], bl[p * 4 + 1], bl[p * 4 + 2], bl[p * 4 + 3]);
            }
            #pragma unroll
            for (int t = 0; t < 2; t++)
                #pragma unroll
                for (int u = 0; u < 4; u++) {
                    mma16816(acc[t][u], ah[t], &bh[u * 2]);
                    mma16816(acc[t][u], ah[t], &bl[u * 2]);
                    mma16816(acc[t][u], al[t], &bh[u * 2]);
                }
        }
        __syncthreads();
    }

    #pragma unroll
    for (int t = 0; t < 2; t++) {
        const int rbase = m0 + wm * 32 + t * 16 + (lane >> 2);
        #pragma unroll
        for (int u = 0; u < 4; u++) {
            const int gn = n0 + wn * 32 + u * 8 + (lane & 3) * 2;
            const float b0 = __ldg(&bias[gn]);
            const float b1 = __ldg(&bias[gn + 1]);
            #pragma unroll
            for (int h = 0; h < 2; h++) {
                float v0 = acc[t][u][h * 2 + 0] + b0;
                float v1 = acc[t][u][h * 2 + 1] + b1;
                if (relu) { v0 = fmaxf(v0, 0.f); v1 = fmaxf(v1, 0.f); }
                const size_t idx = (size_t)(rbase + h * 8) * ldc + gn;
                if (splitOut) {
                    __nv_bfloat16 h0, l0, h1, l1;
                    split_f32(v0, h0, l0); split_f32(v1, h1, l1);
                    *reinterpret_cast<__nv_bfloat162*>(Ch + idx) = __halves2bfloat162(h0, h1);
                    *reinterpret_cast<__nv_bfloat162*>(Cl + idx) = __halves2bfloat162(l0, l1);
                } else {
                    *reinterpret_cast<float2*>(Cf + idx) = make_float2(v0, v1);
                }
            }
        }
    }
}

// ======== fused gather + interaction: one block per sample =================
__global__ void __launch_bounds__(128) gather_interact_kernel(
    const float* __restrict__ x, const float* __restrict__ emb,
    const void* __restrict__ lsi,
    __nv_bfloat16* __restrict__ Rh, __nv_bfloat16* __restrict__ Rl)
{
    __shared__ float s[27][65];
    const int b   = blockIdx.x;
    const int tid = threadIdx.x;
    const int wid = tid >> 5;
    const int lane = tid & 31;
    const int is64 = g_idx_is64;
    const long long* ip64 = (const long long*)lsi;
    const int*       ip32 = (const int*)lsi;

    if (tid < 32) {
        float2 v = *reinterpret_cast<const float2*>(x + (size_t)b * 64 + tid * 2);
        s[0][tid * 2] = v.x; s[0][tid * 2 + 1] = v.y;
    }
    for (int t = wid; t < NTAB; t += 4) {
        const size_t base = ((size_t)t * B_SZ + b) * 4;
        float2 acc = make_float2(0.f, 0.f);
        #pragma unroll
        for (int l = 0; l < 4; l++) {
            long long ix = is64 ? ip64[base + l] : (long long)ip32[base + l];
            if (ix < 0) ix = 0;
            if (ix >= VOCAB) ix = VOCAB - 1;
            const float2* row = reinterpret_cast<const float2*>(
                emb + ((size_t)t * VOCAB + (size_t)ix) * EMB_D);
            float2 v = __ldg(&row[lane]);
            acc.x += v.x; acc.y += v.y;
        }
        s[1 + t][lane * 2] = acc.x; s[1 + t][lane * 2 + 1] = acc.y;
    }
    __syncthreads();

    __nv_bfloat16* Rbh = Rh + (size_t)b * 448;
    __nv_bfloat16* Rbl = Rl + (size_t)b * 448;

    if (tid < 64) {
        __nv_bfloat16 h, l; split_f32(s[0][tid], h, l);
        Rbh[tid] = h; Rbl[tid] = l;
    }
    for (int c = 415 + tid; c < 448; c += 128) {
        Rbh[c] = __float2bfloat16(0.f); Rbl[c] = __float2bfloat16(0.f);
    }

    if (tid < 105) {
        int ti = (int)(0.5f * (sqrtf(8.0f * (float)tid + 1.0f) - 1.0f));
        while (ti * (ti + 1) / 2 > tid) --ti;
        while ((ti + 1) * (ti + 2) / 2 <= tid) ++ti;
        const int tj = tid - ti * (ti + 1) / 2;
        const int i0 = 2 * ti, i1 = 2 * ti + 1;
        const int j0 = 2 * tj, j1 = 2 * tj + 1;
        const float* si0 = s[i0];
        const float* si1 = s[(i1 < 27) ? i1 : 26];   // clamp (values unused when OOB)
        const float* sj0 = s[j0];
        const float* sj1 = s[(j1 < 27) ? j1 : 26];   // clamp (values unused when OOB)
        float d00 = 0.f, d01 = 0.f, d10 = 0.f, d11 = 0.f;
        #pragma unroll
        for (int k = 0; k < 64; k++) {
            const float a0 = si0[k], a1 = si1[k];
            const float b0 = sj0[k], b1 = sj1[k];
            d00 += a0 * b0; d01 += a0 * b1;
            d10 += a1 * b0; d11 += a1 * b1;
        }
        __nv_bfloat16 h, l;
        const bool offd = (ti > tj);
        const bool row1 = (i1 < 27);
        if (offd) {
            split_f32(d00, h, l);
            { const int p = i0 * (i0 - 1) / 2 + j0; Rbh[64 + p] = h; Rbl[64 + p] = l; }
            split_f32(d01, h, l);
            { const int p = i0 * (i0 - 1) / 2 + j1; Rbh[64 + p] = h; Rbl[64 + p] = l; }
        }
        if (row1) {
            split_f32(d10, h, l);
            { const int p = i1 * (i1 - 1) / 2 + j0; Rbh[64 + p] = h; Rbl[64 + p] = l; }
            if (offd) {
                split_f32(d11, h, l);
                { const int p = i1 * (i1 - 1) / 2 + j1; Rbh[64 + p] = h; Rbl[64 + p] = l; }
            }
        }
    }
}

// ======================= final layer + sigmoid ==============================
__global__ void __launch_bounds__(256) top_final_kernel(
    const float* __restrict__ Z, const float* __restrict__ W,
    const float* __restrict__ bias, float* __restrict__ out)
{
    const int b = blockIdx.x * 8 + (threadIdx.x >> 5);
    const int lane = threadIdx.x & 31;
    const float* zr = Z + (size_t)b * 256;
    float acc = 0.f;
    #pragma unroll
    for (int k = lane; k < 256; k += 32) acc += zr[k] * W[k];
    #pragma unroll
    for (int off = 16; off > 0; off >>= 1)
        acc += __shfl_xor_sync(0xFFFFFFFFu, acc, off);
    if (lane == 0) {
        const float v = acc + bias[0];
        out[b] = 1.f / (1.f + expf(-v));
    }
}

// ======================= launch =============================================
extern "C" void kernel_launch(void* const* d_in, const int* in_sizes, int n_in,
                              void* d_out, int out_size)
{
    (void)n_in; (void)out_size;
    const float* dense_x = (const float*)d_in[0];
    const void*  lsi     = d_in[2];
    const float* emb     = (const float*)d_in[3];

    const float *bW0, *bb0, *bW1, *bb1, *bW2, *bb2;
    const float *tW0, *tb0, *tW1, *tb1, *tW2, *tb2;
    if (in_sizes[6] == 512 * 415) {
        bW0 = (const float*)d_in[4];  bb0 = (const float*)d_in[5];
        tW0 = (const float*)d_in[6];  tb0 = (const float*)d_in[7];
        bW1 = (const float*)d_in[8];  bb1 = (const float*)d_in[9];
        tW1 = (const float*)d_in[10]; tb1 = (const float*)d_in[11];
        bW2 = (const float*)d_in[12]; bb2 = (const float*)d_in[13];
        tW2 = (const float*)d_in[14]; tb2 = (const float*)d_in[15];
    } else {
        bW0 = (const float*)d_in[4];  bb0 = (const float*)d_in[5];
        bW1 = (const float*)d_in[6];  bb1 = (const float*)d_in[7];
        bW2 = (const float*)d_in[8];  bb2 = (const float*)d_in[9];
        tW0 = (const float*)d_in[10]; tb0 = (const float*)d_in[11];
        tW1 = (const float*)d_in[12]; tb1 = (const float*)d_in[13];
        tW2 = (const float*)d_in[14]; tb2 = (const float*)d_in[15];
    }

    float *x, *z2;
    __nv_bfloat16 *x1h, *x1l, *x2h, *x2l, *Rh, *Rl, *z1h, *z1l;
    __nv_bfloat16 *bW1h, *bW1l, *bW2h, *bW2l, *tW0h, *tW0l, *tW1h, *tW1l;
    cudaGetSymbolAddress((void**)&x,    g_x);
    cudaGetSymbolAddress((void**)&z2,   g_z2);
    cudaGetSymbolAddress((void**)&x1h,  g_x1h);  cudaGetSymbolAddress((void**)&x1l, g_x1l);
    cudaGetSymbolAddress((void**)&x2h,  g_x2h);  cudaGetSymbolAddress((void**)&x2l, g_x2l);
    cudaGetSymbolAddress((void**)&Rh,   g_Rh);   cudaGetSymbolAddress((void**)&Rl,  g_Rl);
    cudaGetSymbolAddress((void**)&z1h,  g_z1h);  cudaGetSymbolAddress((void**)&z1l, g_z1l);
    cudaGetSymbolAddress((void**)&bW1h, g_bW1h); cudaGetSymbolAddress((void**)&bW1l, g_bW1l);
    cudaGetSymbolAddress((void**)&bW2h, g_bW2h); cudaGetSymbolAddress((void**)&bW2l, g_bW2l);
    cudaGetSymbolAddress((void**)&tW0h, g_tW0h); cudaGetSymbolAddress((void**)&tW0l, g_tW0l);
    cudaGetSymbolAddress((void**)&tW1h, g_tW1h); cudaGetSymbolAddress((void**)&tW1l, g_tW1l);

    const int SMEM = 2 * 49152;   // 96KB -> 2 CTA/SM
    cudaFuncSetAttribute(gemm_mma, cudaFuncAttributeMaxDynamicSharedMemorySize, SMEM);

    // launch 0: fused prep (detect + all weight pad/splits)
    prep_kernel<<<1985, 256>>>(bW1, bW2, tW0, tW1, (const int*)lsi,
                               bW1h, bW1l, bW2h, bW2l, tW0h, tW0l, tW1h, tW1l);

    // launches 1-3: bottom MLP -> compact x[B,64]
    bot0_kernel<<<B_SZ / 16, 256>>>(dense_x, bW0, bb0, x1h, x1l);
    gemm_mma<<<dim3(4, 128), 256, SMEM>>>(x1h, x1l, bW1h, bW1l, bb1, 512, 8,
                                          nullptr, x2h, x2l, 256, 1, 1);
    gemm_mma<<<dim3(1, 128), 256, SMEM>>>(x2h, x2l, bW2h, bW2l, bb2, 256, 4,
                                          x, nullptr, nullptr, 64, 1, 0);

    // launch 4: fused gather + interaction -> split R[B,448]
    gather_interact_kernel<<<B_SZ, 128>>>(x, emb, lsi, Rh, Rl);

    // launch 5: top L0 (the big one -- lands on ncu -s 5)
    gemm_mma<<<dim3(8, 128), 256, SMEM>>>(Rh, Rl, tW0h, tW0l, tb0, 448, 7,
                                          nullptr, z1h, z1l, 512, 1, 1);
    gemm_mma<<<dim3(4, 128), 256, SMEM>>>(z1h, z1l, tW1h, tW1l, tb1, 512, 8,
                                          z2, nullptr, nullptr, 256, 1, 0);
    top_final_kernel<<<B_SZ / 8, 256>>>(z2, tW2, tb2, (float*)d_out);
}

// round 9
// speedup vs baseline: 1.0992x; 1.0302x over previous
#include <cuda_runtime.h>
#include <cuda_bf16.h>
#include <math.h>
#include <stdint.h>

#define B_SZ   16384
#define NTAB   26
#define VOCAB  100000
#define EMB_D  64

// ======================= scratch (device globals) ==========================
__device__ __align__(256) float g_x [B_SZ * 64];            // bot MLP out fp32
__device__ __align__(256) float g_z2[B_SZ * 256];           // top L1 out fp32

__device__ __align__(256) __nv_bfloat16 g_x1h[B_SZ * 512];
__device__ __align__(256) __nv_bfloat16 g_x1l[B_SZ * 512];
__device__ __align__(256) __nv_bfloat16 g_x2h[B_SZ * 256];
__device__ __align__(256) __nv_bfloat16 g_x2l[B_SZ * 256];
__device__ __align__(256) __nv_bfloat16 g_Rh [B_SZ * 448];
__device__ __align__(256) __nv_bfloat16 g_Rl [B_SZ * 448];
__device__ __align__(256) __nv_bfloat16 g_z1h[B_SZ * 512];
__device__ __align__(256) __nv_bfloat16 g_z1l[B_SZ * 512];

__device__ __align__(256) __nv_bfloat16 g_bW1h[256 * 512];
__device__ __align__(256) __nv_bfloat16 g_bW1l[256 * 512];
__device__ __align__(256) __nv_bfloat16 g_bW2h[64 * 256];
__device__ __align__(256) __nv_bfloat16 g_bW2l[64 * 256];
__device__ __align__(256) __nv_bfloat16 g_tW0h[512 * 448];
__device__ __align__(256) __nv_bfloat16 g_tW0l[512 * 448];
__device__ __align__(256) __nv_bfloat16 g_tW1h[256 * 512];
__device__ __align__(256) __nv_bfloat16 g_tW1l[256 * 512];

__device__ int g_idx_is64;

// ======================= helpers ============================================
__device__ __forceinline__ uint32_t smem_u32(const void* p) {
    uint32_t a;
    asm("{ .reg .u64 t; cvta.to.shared.u64 t, %1; cvt.u32.u64 %0, t; }"
        : "=r"(a) : "l"(p));
    return a;
}
__device__ __forceinline__ void cpa16(uint32_t saddr, const void* g) {
    asm volatile("cp.async.cg.shared.global [%0], [%1], 16;" :: "r"(saddr), "l"(g));
}
__device__ __forceinline__ void cpa_commit() {
    asm volatile("cp.async.commit_group;" ::: "memory");
}
__device__ __forceinline__ void cpa_wait1() {
    asm volatile("cp.async.wait_group 1;" ::: "memory");
}
__device__ __forceinline__ void cpa_wait0() {
    asm volatile("cp.async.wait_group 0;" ::: "memory");
}
__device__ __forceinline__ void ldm_x4(uint32_t a, uint32_t& r0, uint32_t& r1,
                                       uint32_t& r2, uint32_t& r3) {
    asm volatile("ldmatrix.sync.aligned.m8n8.x4.shared.b16 {%0,%1,%2,%3}, [%4];"
                 : "=r"(r0), "=r"(r1), "=r"(r2), "=r"(r3) : "r"(a));
}
__device__ __forceinline__ void mma16816(float* c, const uint32_t* a,
                                         const uint32_t* b) {
    asm volatile(
        "mma.sync.aligned.m16n8k16.row.col.f32.bf16.bf16.f32 "
        "{%0,%1,%2,%3}, {%4,%5,%6,%7}, {%8,%9}, {%0,%1,%2,%3};"
        : "+f"(c[0]), "+f"(c[1]), "+f"(c[2]), "+f"(c[3])
        : "r"(a[0]), "r"(a[1]), "r"(a[2]), "r"(a[3]), "r"(b[0]), "r"(b[1]));
}
__device__ __forceinline__ void split_f32(float v, __nv_bfloat16& h, __nv_bfloat16& l) {
    h = __float2bfloat16(v);
    l = __float2bfloat16(v - __bfloat162float(h));
}

// ===== launch 0: fused prep (pad/split weights + idx detect) + bot layer 0 ==
__device__ __forceinline__ void padsplit_one(const float* W, __nv_bfloat16* Wh,
                                             __nv_bfloat16* Wl, int i,
                                             int Kin, int Kpad) {
    const int n = i / Kpad;
    const int k = i - n * Kpad;
    const float v = (k < Kin) ? W[n * Kin + k] : 0.f;
    __nv_bfloat16 h, l; split_f32(v, h, l);
    Wh[i] = h; Wl[i] = l;
}

__global__ void __launch_bounds__(256) prep_bot0_kernel(
    const float* __restrict__ X, const float* __restrict__ bW0,
    const float* __restrict__ bb0,
    __nv_bfloat16* __restrict__ Yh, __nv_bfloat16* __restrict__ Yl,
    const float* __restrict__ bW1, const float* __restrict__ bW2,
    const float* __restrict__ tW0, const float* __restrict__ tW1,
    const int* __restrict__ lsi32,
    __nv_bfloat16* __restrict__ bW1h, __nv_bfloat16* __restrict__ bW1l,
    __nv_bfloat16* __restrict__ bW2h, __nv_bfloat16* __restrict__ bW2l,
    __nv_bfloat16* __restrict__ tW0h, __nv_bfloat16* __restrict__ tW0l,
    __nv_bfloat16* __restrict__ tW1h, __nv_bfloat16* __restrict__ tW1l)
{
    const int bid = blockIdx.x;
    const int tid = threadIdx.x;
    if (bid < 1024) {
        // ---- bot layer 0: rows bid*16 .. bid*16+15 ----
        __shared__ float sW[512 * 13];
        __shared__ float sb[512];
        __shared__ float sx[16 * 13];
        const int r0 = bid * 16;
        for (int i = tid; i < 512 * 13; i += 256) sW[i] = bW0[i];
        for (int i = tid; i < 512; i += 256) sb[i] = bb0[i];
        for (int i = tid; i < 16 * 13; i += 256) sx[i] = X[r0 * 13 + i];
        __syncthreads();
        for (int o = tid; o < 16 * 512; o += 256) {
            const int r = o >> 9;
            const int c = o & 511;
            float acc = sb[c];
            #pragma unroll
            for (int k = 0; k < 13; k++) acc += sx[r * 13 + k] * sW[c * 13 + k];
            acc = fmaxf(acc, 0.f);
            __nv_bfloat16 h, l; split_f32(acc, h, l);
            const size_t idx = (size_t)(r0 + r) * 512 + c;
            Yh[idx] = h; Yl[idx] = l;
        }
        return;
    }
    if (bid == 3008) {
        // ---- index dtype detect ----
        if (tid < 32) {
            int any = 0;
            for (int k = tid; k < 2048; k += 32)
                if (lsi32[2 * k + 1] != 0) any = 1;
            any = __any_sync(0xFFFFFFFFu, any);
            if (tid == 0) g_idx_is64 = any ? 0 : 1;
        }
        return;
    }
    // ---- weight pad/split ----
    const int i = (bid - 1024) * 256 + tid;
    if (i < 131072) {
        padsplit_one(bW1, bW1h, bW1l, i, 512, 512);                 // 256x512
    } else if (i < 147456) {
        padsplit_one(bW2, bW2h, bW2l, i - 131072, 256, 256);        // 64x256
    } else if (i < 376832) {
        padsplit_one(tW0, tW0h, tW0l, i - 147456, 415, 448);        // 512x448
    } else {
        padsplit_one(tW1, tW1h, tW1l, i - 376832, 512, 512);        // 256x512
    }
}

// ======================= mma.sync bf16x3 GEMM (NT=64, 2 CTA/SM) =============
#define STG 49152u
__device__ __forceinline__ uint32_t swz(int row, int chunk) {
    return (uint32_t)(row * 128 + ((chunk ^ (row & 7)) * 16));
}

__global__ void __launch_bounds__(256) gemm_mma(
    const __nv_bfloat16* __restrict__ Ah, const __nv_bfloat16* __restrict__ Al,
    const __nv_bfloat16* __restrict__ Wh, const __nv_bfloat16* __restrict__ Wl,
    const float* __restrict__ bias, int K, int NC,
    float* __restrict__ Cf,
    __nv_bfloat16* __restrict__ Ch, __nv_bfloat16* __restrict__ Cl,
    int ldc, int relu, int splitOut)
{
    extern __shared__ char smem[];
    const uint32_t sb = smem_u32(smem);
    const int tid  = threadIdx.x;
    const int lane = tid & 31;
    const int wid  = tid >> 5;
    const int wm   = wid >> 1;
    const int wn   = wid & 1;
    const int m0 = blockIdx.y * 128;
    const int n0 = blockIdx.x * 64;
    const size_t rowB = (size_t)K * 2;

    const char* gAh = (const char*)Ah + (size_t)m0 * rowB;
    const char* gAl = (const char*)Al + (size_t)m0 * rowB;
    const char* gWh = (const char*)Wh + (size_t)n0 * rowB;
    const char* gWl = (const char*)Wl + (size_t)n0 * rowB;

    float acc[2][4][4];
    #pragma unroll
    for (int t = 0; t < 2; t++)
        #pragma unroll
        for (int u = 0; u < 4; u++)
            #pragma unroll
            for (int v = 0; v < 4; v++) acc[t][u][v] = 0.f;

    auto load_stage = [&](int c) {
        const uint32_t so = sb + (uint32_t)(c & 1) * STG;
        const size_t kb = (size_t)c * 128;
        #pragma unroll
        for (int i = 0; i < 4; i++) {
            const int e = tid + i * 256;
            const int row = e >> 3;
            const int ch  = e & 7;
            const size_t gs = (size_t)row * rowB + kb + ch * 16;
            const uint32_t d = swz(row, ch);
            cpa16(so + d,          gAh + gs);
            cpa16(so + 16384 + d,  gAl + gs);
        }
        #pragma unroll
        for (int i = 0; i < 2; i++) {
            const int e = tid + i * 256;
            const int row = e >> 3;
            const int ch  = e & 7;
            const size_t gs = (size_t)row * rowB + kb + ch * 16;
            const uint32_t d = swz(row, ch);
            cpa16(so + 32768 + d, gWh + gs);
            cpa16(so + 40960 + d, gWl + gs);
        }
        cpa_commit();
    };

    load_stage(0);
    for (int c = 0; c < NC; ++c) {
        if (c + 1 < NC) load_stage(c + 1);
        if (c + 1 < NC) cpa_wait1(); else cpa_wait0();
        __syncthreads();

        const uint32_t so = sb + (uint32_t)(c & 1) * STG;
        const uint32_t sAhB = so, sAlB = so + 16384;
        const uint32_t sWhB = so + 32768, sWlB = so + 40960;

        #pragma unroll
        for (int kk = 0; kk < 4; kk++) {
            uint32_t ah[2][4], al[2][4], bh[8], bl[8];
            #pragma unroll
            for (int t = 0; t < 2; t++) {
                const int row = wm * 32 + t * 16 + (lane & 15);
                const int ch  = kk * 2 + (lane >> 4);
                const uint32_t d = swz(row, ch);
                ldm_x4(sAhB + d, ah[t][0], ah[t][1], ah[t][2], ah[t][3]);
                ldm_x4(sAlB + d, al[t][0], al[t][1], al[t][2], al[t][3]);
            }
            #pragma unroll
            for (int p = 0; p < 2; p++) {
                const int row = wn * 32 + p * 16 + ((lane >> 4) & 1) * 8 + (lane & 7);
                const int ch  = kk * 2 + ((lane >> 3) & 1);
                const uint32_t d = swz(row, ch);
                ldm_x4(sWhB + d, bh[p * 4 + 0], bh[p * 4 + 1], bh[p * 4 + 2], bh[p * 4 + 3]);
                ldm_x4(sWlB + d, bl[p * 4 + 0], bl[p * 4 + 1], bl[p * 4 + 2], bl[p * 4 + 3]);
            }
            #pragma unroll
            for (int t = 0; t < 2; t++)
                #pragma unroll
                for (int u = 0; u < 4; u++) {
                    mma16816(acc[t][u], ah[t], &bh[u * 2]);
                    mma16816(acc[t][u], ah[t], &bl[u * 2]);
                    mma16816(acc[t][u], al[t], &bh[u * 2]);
                }
        }
        __syncthreads();
    }

    #pragma unroll
    for (int t = 0; t < 2; t++) {
        const int rbase = m0 + wm * 32 + t * 16 + (lane >> 2);
        #pragma unroll
        for (int u = 0; u < 4; u++) {
            const int gn = n0 + wn * 32 + u * 8 + (lane & 3) * 2;
            const float b0 = __ldg(&bias[gn]);
            const float b1 = __ldg(&bias[gn + 1]);
            #pragma unroll
            for (int h = 0; h < 2; h++) {
                float v0 = acc[t][u][h * 2 + 0] + b0;
                float v1 = acc[t][u][h * 2 + 1] + b1;
                if (relu) { v0 = fmaxf(v0, 0.f); v1 = fmaxf(v1, 0.f); }
                const size_t idx = (size_t)(rbase + h * 8) * ldc + gn;
                if (splitOut) {
                    __nv_bfloat16 h0, l0, h1, l1;
                    split_f32(v0, h0, l0); split_f32(v1, h1, l1);
                    *reinterpret_cast<__nv_bfloat162*>(Ch + idx) = __halves2bfloat162(h0, h1);
                    *reinterpret_cast<__nv_bfloat162*>(Cl + idx) = __halves2bfloat162(l0, l1);
                } else {
                    *reinterpret_cast<float2*>(Cf + idx) = make_float2(v0, v1);
                }
            }
        }
    }
}

// ======== fused gather + interaction (3x3 register tiling) =================
// 45 tiles over 9 row-groups of 3; off-diag tiles: 6 row-reads for 9 dots.
__global__ void __launch_bounds__(128) gather_interact_kernel(
    const float* __restrict__ x, const float* __restrict__ emb,
    const void* __restrict__ lsi,
    __nv_bfloat16* __restrict__ Rh, __nv_bfloat16* __restrict__ Rl)
{
    __shared__ float s[27][65];
    const int b   = blockIdx.x;
    const int tid = threadIdx.x;
    const int wid = tid >> 5;
    const int lane = tid & 31;
    const int is64 = g_idx_is64;
    const long long* ip64 = (const long long*)lsi;
    const int*       ip32 = (const int*)lsi;

    if (tid < 32) {
        float2 v = *reinterpret_cast<const float2*>(x + (size_t)b * 64 + tid * 2);
        s[0][tid * 2] = v.x; s[0][tid * 2 + 1] = v.y;
    }
    for (int t = wid; t < NTAB; t += 4) {
        const size_t base = ((size_t)t * B_SZ + b) * 4;
        float2 acc = make_float2(0.f, 0.f);
        #pragma unroll
        for (int l = 0; l < 4; l++) {
            long long ix = is64 ? ip64[base + l] : (long long)ip32[base + l];
            if (ix < 0) ix = 0;
            if (ix >= VOCAB) ix = VOCAB - 1;
            const float2* row = reinterpret_cast<const float2*>(
                emb + ((size_t)t * VOCAB + (size_t)ix) * EMB_D);
            float2 v = __ldg(&row[lane]);
            acc.x += v.x; acc.y += v.y;
        }
        s[1 + t][lane * 2] = acc.x; s[1 + t][lane * 2 + 1] = acc.y;
    }
    __syncthreads();

    __nv_bfloat16* Rbh = Rh + (size_t)b * 448;
    __nv_bfloat16* Rbl = Rl + (size_t)b * 448;

    if (tid < 64) {
        __nv_bfloat16 h, l; split_f32(s[0][tid], h, l);
        Rbh[tid] = h; Rbl[tid] = l;
    }
    for (int c = 415 + tid; c < 448; c += 128) {
        Rbh[c] = __float2bfloat16(0.f); Rbl[c] = __float2bfloat16(0.f);
    }

    // 3x3 tiles: 9 groups of 3 rows; 45 (gi>=gj) tiles
    if (tid < 45) {
        int gi = (int)(0.5f * (sqrtf(8.0f * (float)tid + 1.0f) - 1.0f));
        while (gi * (gi + 1) / 2 > tid) --gi;
        while ((gi + 1) * (gi + 2) / 2 <= tid) ++gi;
        const int gj = tid - gi * (gi + 1) / 2;
        const int i0 = 3 * gi, j0 = 3 * gj;
        const float* si0 = s[i0];
        const float* si1 = s[i0 + 1];
        const float* si2 = s[i0 + 2];
        const float* sj0 = s[j0];
        const float* sj1 = s[j0 + 1];
        const float* sj2 = s[j0 + 2];
        float d[3][3];
        #pragma unroll
        for (int a = 0; a < 3; a++)
            #pragma unroll
            for (int c2 = 0; c2 < 3; c2++) d[a][c2] = 0.f;
        for (int k = 0; k < 64; k++) {
            const float a0 = si0[k], a1 = si1[k], a2 = si2[k];
            const float b0 = sj0[k], b1 = sj1[k], b2 = sj2[k];
            d[0][0] += a0 * b0; d[0][1] += a0 * b1; d[0][2] += a0 * b2;
            d[1][0] += a1 * b0; d[1][1] += a1 * b1; d[1][2] += a1 * b2;
            d[2][0] += a2 * b0; d[2][1] += a2 * b1; d[2][2] += a2 * b2;
        }
        #pragma unroll
        for (int a = 0; a < 3; a++) {
            const int i = i0 + a;
            #pragma unroll
            for (int c2 = 0; c2 < 3; c2++) {
                const int j = j0 + c2;
                if (i > j) {
                    __nv_bfloat16 h, l; split_f32(d[a][c2], h, l);
                    const int p = i * (i - 1) / 2 + j;
                    Rbh[64 + p] = h; Rbl[64 + p] = l;
                }
            }
        }
    }
}

// ======================= final layer + sigmoid ==============================
__global__ void __launch_bounds__(256) top_final_kernel(
    const float* __restrict__ Z, const float* __restrict__ W,
    const float* __restrict__ bias, float* __restrict__ out)
{
    const int b = blockIdx.x * 8 + (threadIdx.x >> 5);
    const int lane = threadIdx.x & 31;
    const float* zr = Z + (size_t)b * 256;
    float acc = 0.f;
    #pragma unroll
    for (int k = lane; k < 256; k += 32) acc += zr[k] * W[k];
    #pragma unroll
    for (int off = 16; off > 0; off >>= 1)
        acc += __shfl_xor_sync(0xFFFFFFFFu, acc, off);
    if (lane == 0) {
        const float v = acc + bias[0];
        out[b] = 1.f / (1.f + expf(-v));
    }
}

// ======================= launch =============================================
extern "C" void kernel_launch(void* const* d_in, const int* in_sizes, int n_in,
                              void* d_out, int out_size)
{
    (void)n_in; (void)out_size;
    const float* dense_x = (const float*)d_in[0];
    const void*  lsi     = d_in[2];
    const float* emb     = (const float*)d_in[3];

    const float *bW0, *bb0, *bW1, *bb1, *bW2, *bb2;
    const float *tW0, *tb0, *tW1, *tb1, *tW2, *tb2;
    if (in_sizes[6] == 512 * 415) {
        bW0 = (const float*)d_in[4];  bb0 = (const float*)d_in[5];
        tW0 = (const float*)d_in[6];  tb0 = (const float*)d_in[7];
        bW1 = (const float*)d_in[8];  bb1 = (const float*)d_in[9];
        tW1 = (const float*)d_in[10]; tb1 = (const float*)d_in[11];
        bW2 = (const float*)d_in[12]; bb2 = (const float*)d_in[13];
        tW2 = (const float*)d_in[14]; tb2 = (const float*)d_in[15];
    } else {
        bW0 = (const float*)d_in[4];  bb0 = (const float*)d_in[5];
        bW1 = (const float*)d_in[6];  bb1 = (const float*)d_in[7];
        bW2 = (const float*)d_in[8];  bb2 = (const float*)d_in[9];
        tW0 = (const float*)d_in[10]; tb0 = (const float*)d_in[11];
        tW1 = (const float*)d_in[12]; tb1 = (const float*)d_in[13];
        tW2 = (const float*)d_in[14]; tb2 = (const float*)d_in[15];
    }

    float *x, *z2;
    __nv_bfloat16 *x1h, *x1l, *x2h, *x2l, *Rh, *Rl, *z1h, *z1l;
    __nv_bfloat16 *bW1h, *bW1l, *bW2h, *bW2l, *tW0h, *tW0l, *tW1h, *tW1l;
    cudaGetSymbolAddress((void**)&x,    g_x);
    cudaGetSymbolAddress((void**)&z2,   g_z2);
    cudaGetSymbolAddress((void**)&x1h,  g_x1h);  cudaGetSymbolAddress((void**)&x1l, g_x1l);
    cudaGetSymbolAddress((void**)&x2h,  g_x2h);  cudaGetSymbolAddress((void**)&x2l, g_x2l);
    cudaGetSymbolAddress((void**)&Rh,   g_Rh);   cudaGetSymbolAddress((void**)&Rl,  g_Rl);
    cudaGetSymbolAddress((void**)&z1h,  g_z1h);  cudaGetSymbolAddress((void**)&z1l, g_z1l);
    cudaGetSymbolAddress((void**)&bW1h, g_bW1h); cudaGetSymbolAddress((void**)&bW1l, g_bW1l);
    cudaGetSymbolAddress((void**)&bW2h, g_bW2h); cudaGetSymbolAddress((void**)&bW2l, g_bW2l);
    cudaGetSymbolAddress((void**)&tW0h, g_tW0h); cudaGetSymbolAddress((void**)&tW0l, g_tW0l);
    cudaGetSymbolAddress((void**)&tW1h, g_tW1h); cudaGetSymbolAddress((void**)&tW1l, g_tW1l);

    const int SMEM = 2 * 49152;   // 96KB -> 2 CTA/SM
    cudaFuncSetAttribute(gemm_mma, cudaFuncAttributeMaxDynamicSharedMemorySize, SMEM);

    // launch 0: fused prep (pad/split + detect) + bot layer 0
    prep_bot0_kernel<<<3009, 256>>>(dense_x, bW0, bb0, x1h, x1l,
                                    bW1, bW2, tW0, tW1, (const int*)lsi,
                                    bW1h, bW1l, bW2h, bW2l,
                                    tW0h, tW0l, tW1h, tW1l);

    // launches 1-2: rest of bottom MLP -> compact x[B,64]
    gemm_mma<<<dim3(4, 128), 256, SMEM>>>(x1h, x1l, bW1h, bW1l, bb1, 512, 8,
                                          nullptr, x2h, x2l, 256, 1, 1);
    gemm_mma<<<dim3(1, 128), 256, SMEM>>>(x2h, x2l, bW2h, bW2l, bb2, 256, 4,
                                          x, nullptr, nullptr, 64, 1, 0);

    // launch 3: fused gather + interaction -> split R[B,448]
    gather_interact_kernel<<<B_SZ, 128>>>(x, emb, lsi, Rh, Rl);

    // launches 4-6: top MLP
    gemm_mma<<<dim3(8, 128), 256, SMEM>>>(Rh, Rl, tW0h, tW0l, tb0, 448, 7,
                                          nullptr, z1h, z1l, 512, 1, 1);
    gemm_mma<<<dim3(4, 128), 256, SMEM>>>(z1h, z1l, tW1h, tW1l, tb1, 512, 8,
                                          z2, nullptr, nullptr, 256, 1, 0);
    top_final_kernel<<<B_SZ / 8, 256>>>(z2, tW2, tb2, (float*)d_out);
}

// round 10
// speedup vs baseline: 1.1451x; 1.0418x over previous
#include <cuda_runtime.h>
#include <cuda_bf16.h>
#include <math.h>
#include <stdint.h>

#define B_SZ   16384
#define NTAB   26
#define VOCAB  100000
#define EMB_D  64

// ======================= scratch (device globals) ==========================
__device__ __align__(256) float g_x [B_SZ * 64];            // bot MLP out fp32
__device__ __align__(256) float g_z2[B_SZ * 256];           // top L1 out fp32

__device__ __align__(256) __nv_bfloat16 g_x1h[B_SZ * 512];
__device__ __align__(256) __nv_bfloat16 g_x1l[B_SZ * 512];
__device__ __align__(256) __nv_bfloat16 g_x2h[B_SZ * 256];
__device__ __align__(256) __nv_bfloat16 g_x2l[B_SZ * 256];
__device__ __align__(256) __nv_bfloat16 g_Rh [B_SZ * 448];
__device__ __align__(256) __nv_bfloat16 g_Rl [B_SZ * 448];
__device__ __align__(256) __nv_bfloat16 g_z1h[B_SZ * 512];
__device__ __align__(256) __nv_bfloat16 g_z1l[B_SZ * 512];

__device__ __align__(256) __nv_bfloat16 g_bW1h[256 * 512];
__device__ __align__(256) __nv_bfloat16 g_bW1l[256 * 512];
__device__ __align__(256) __nv_bfloat16 g_bW2h[64 * 256];
__device__ __align__(256) __nv_bfloat16 g_bW2l[64 * 256];
__device__ __align__(256) __nv_bfloat16 g_tW0h[512 * 448];
__device__ __align__(256) __nv_bfloat16 g_tW0l[512 * 448];
__device__ __align__(256) __nv_bfloat16 g_tW1h[256 * 512];
__device__ __align__(256) __nv_bfloat16 g_tW1l[256 * 512];

__device__ int g_idx_is64;

// ======================= helpers ============================================
__device__ __forceinline__ uint32_t smem_u32(const void* p) {
    uint32_t a;
    asm("{ .reg .u64 t; cvta.to.shared.u64 t, %1; cvt.u32.u64 %0, t; }"
        : "=r"(a) : "l"(p));
    return a;
}
__device__ __forceinline__ void cpa16(uint32_t saddr, const void* g) {
    asm volatile("cp.async.cg.shared.global [%0], [%1], 16;" :: "r"(saddr), "l"(g));
}
__device__ __forceinline__ void cpa_commit() {
    asm volatile("cp.async.commit_group;" ::: "memory");
}
__device__ __forceinline__ void cpa_wait1() {
    asm volatile("cp.async.wait_group 1;" ::: "memory");
}
__device__ __forceinline__ void cpa_wait0() {
    asm volatile("cp.async.wait_group 0;" ::: "memory");
}
__device__ __forceinline__ void ldm_x4(uint32_t a, uint32_t& r0, uint32_t& r1,
                                       uint32_t& r2, uint32_t& r3) {
    asm volatile("ldmatrix.sync.aligned.m8n8.x4.shared.b16 {%0,%1,%2,%3}, [%4];"
                 : "=r"(r0), "=r"(r1), "=r"(r2), "=r"(r3) : "r"(a));
}
__device__ __forceinline__ void mma16816(float* c, const uint32_t* a,
                                         const uint32_t* b) {
    asm volatile(
        "mma.sync.aligned.m16n8k16.row.col.f32.bf16.bf16.f32 "
        "{%0,%1,%2,%3}, {%4,%5,%6,%7}, {%8,%9}, {%0,%1,%2,%3};"
        : "+f"(c[0]), "+f"(c[1]), "+f"(c[2]), "+f"(c[3])
        : "r"(a[0]), "r"(a[1]), "r"(a[2]), "r"(a[3]), "r"(b[0]), "r"(b[1]));
}
__device__ __forceinline__ void split_f32(float v, __nv_bfloat16& h, __nv_bfloat16& l) {
    h = __float2bfloat16(v);
    l = __float2bfloat16(v - __bfloat162float(h));
}

// ===== launch 0: fused prep (pad/split weights + idx detect) + bot layer 0 ==
__device__ __forceinline__ void padsplit_one(const float* W, __nv_bfloat16* Wh,
                                             __nv_bfloat16* Wl, int i,
                                             int Kin, int Kpad) {
    const int n = i / Kpad;
    const int k = i - n * Kpad;
    const float v = (k < Kin) ? W[n * Kin + k] : 0.f;
    __nv_bfloat16 h, l; split_f32(v, h, l);
    Wh[i] = h; Wl[i] = l;
}

__global__ void __launch_bounds__(256) prep_bot0_kernel(
    const float* __restrict__ X, const float* __restrict__ bW0,
    const float* __restrict__ bb0,
    __nv_bfloat16* __restrict__ Yh, __nv_bfloat16* __restrict__ Yl,
    const float* __restrict__ bW1, const float* __restrict__ bW2,
    const float* __restrict__ tW0, const float* __restrict__ tW1,
    const int* __restrict__ lsi32,
    __nv_bfloat16* __restrict__ bW1h, __nv_bfloat16* __restrict__ bW1l,
    __nv_bfloat16* __restrict__ bW2h, __nv_bfloat16* __restrict__ bW2l,
    __nv_bfloat16* __restrict__ tW0h, __nv_bfloat16* __restrict__ tW0l,
    __nv_bfloat16* __restrict__ tW1h, __nv_bfloat16* __restrict__ tW1l)
{
    const int bid = blockIdx.x;
    const int tid = threadIdx.x;
    if (bid < 1024) {
        __shared__ float sW[512 * 13];
        __shared__ float sb[512];
        __shared__ float sx[16 * 13];
        const int r0 = bid * 16;
        for (int i = tid; i < 512 * 13; i += 256) sW[i] = bW0[i];
        for (int i = tid; i < 512; i += 256) sb[i] = bb0[i];
        for (int i = tid; i < 16 * 13; i += 256) sx[i] = X[r0 * 13 + i];
        __syncthreads();
        for (int o = tid; o < 16 * 512; o += 256) {
            const int r = o >> 9;
            const int c = o & 511;
            float acc = sb[c];
            #pragma unroll
            for (int k = 0; k < 13; k++) acc += sx[r * 13 + k] * sW[c * 13 + k];
            acc = fmaxf(acc, 0.f);
            __nv_bfloat16 h, l; split_f32(acc, h, l);
            const size_t idx = (size_t)(r0 + r) * 512 + c;
            Yh[idx] = h; Yl[idx] = l;
        }
        return;
    }
    if (bid == 3008) {
        if (tid < 32) {
            int any = 0;
            for (int k = tid; k < 2048; k += 32)
                if (lsi32[2 * k + 1] != 0) any = 1;
            any = __any_sync(0xFFFFFFFFu, any);
            if (tid == 0) g_idx_is64 = any ? 0 : 1;
        }
        return;
    }
    const int i = (bid - 1024) * 256 + tid;
    if (i < 131072) {
        padsplit_one(bW1, bW1h, bW1l, i, 512, 512);
    } else if (i < 147456) {
        padsplit_one(bW2, bW2h, bW2l, i - 131072, 256, 256);
    } else if (i < 376832) {
        padsplit_one(tW0, tW0h, tW0l, i - 147456, 415, 448);
    } else {
        padsplit_one(tW1, tW1h, tW1l, i - 376832, 512, 512);
    }
}

// ======================= mma.sync bf16x3 GEMM (NT=64, 2 CTA/SM) =============
#define STG 49152u
__device__ __forceinline__ uint32_t swz(int row, int chunk) {
    return (uint32_t)(row * 128 + ((chunk ^ (row & 7)) * 16));
}

__global__ void __launch_bounds__(256) gemm_mma(
    const __nv_bfloat16* __restrict__ Ah, const __nv_bfloat16* __restrict__ Al,
    const __nv_bfloat16* __restrict__ Wh, const __nv_bfloat16* __restrict__ Wl,
    const float* __restrict__ bias, int K, int NC,
    float* __restrict__ Cf,
    __nv_bfloat16* __restrict__ Ch, __nv_bfloat16* __restrict__ Cl,
    int ldc, int relu, int splitOut)
{
    extern __shared__ char smem[];
    const uint32_t sb = smem_u32(smem);
    const int tid  = threadIdx.x;
    const int lane = tid & 31;
    const int wid  = tid >> 5;
    const int wm   = wid >> 1;
    const int wn   = wid & 1;
    const int m0 = blockIdx.y * 128;
    const int n0 = blockIdx.x * 64;
    const size_t rowB = (size_t)K * 2;

    const char* gAh = (const char*)Ah + (size_t)m0 * rowB;
    const char* gAl = (const char*)Al + (size_t)m0 * rowB;
    const char* gWh = (const char*)Wh + (size_t)n0 * rowB;
    const char* gWl = (const char*)Wl + (size_t)n0 * rowB;

    float acc[2][4][4];
    #pragma unroll
    for (int t = 0; t < 2; t++)
        #pragma unroll
        for (int u = 0; u < 4; u++)
            #pragma unroll
            for (int v = 0; v < 4; v++) acc[t][u][v] = 0.f;

    auto load_stage = [&](int c) {
        const uint32_t so = sb + (uint32_t)(c & 1) * STG;
        const size_t kb = (size_t)c * 128;
        #pragma unroll
        for (int i = 0; i < 4; i++) {
            const int e = tid + i * 256;
            const int row = e >> 3;
            const int ch  = e & 7;
            const size_t gs = (size_t)row * rowB + kb + ch * 16;
            const uint32_t d = swz(row, ch);
            cpa16(so + d,          gAh + gs);
            cpa16(so + 16384 + d,  gAl + gs);
        }
        #pragma unroll
        for (int i = 0; i < 2; i++) {
            const int e = tid + i * 256;
            const int row = e >> 3;
            const int ch  = e & 7;
            const size_t gs = (size_t)row * rowB + kb + ch * 16;
            const uint32_t d = swz(row, ch);
            cpa16(so + 32768 + d, gWh + gs);
            cpa16(so + 40960 + d, gWl + gs);
        }
        cpa_commit();
    };

    load_stage(0);
    for (int c = 0; c < NC; ++c) {
        if (c + 1 < NC) load_stage(c + 1);
        if (c + 1 < NC) cpa_wait1(); else cpa_wait0();
        __syncthreads();

        const uint32_t so = sb + (uint32_t)(c & 1) * STG;
        const uint32_t sAhB = so, sAlB = so + 16384;
        const uint32_t sWhB = so + 32768, sWlB = so + 40960;

        #pragma unroll
        for (int kk = 0; kk < 4; kk++) {
            uint32_t ah[2][4], al[2][4], bh[8], bl[8];
            #pragma unroll
            for (int t = 0; t < 2; t++) {
                const int row = wm * 32 + t * 16 + (lane & 15);
                const int ch  = kk * 2 + (lane >> 4);
                const uint32_t d = swz(row, ch);
                ldm_x4(sAhB + d, ah[t][0], ah[t][1], ah[t][2], ah[t][3]);
                ldm_x4(sAlB + d, al[t][0], al[t][1], al[t][2], al[t][3]);
            }
            #pragma unroll
            for (int p = 0; p < 2; p++) {
                const int row = wn * 32 + p * 16 + ((lane >> 4) & 1) * 8 + (lane & 7);
                const int ch  = kk * 2 + ((lane >> 3) & 1);
                const uint32_t d = swz(row, ch);
                ldm_x4(sWhB + d, bh[p * 4 + 0], bh[p * 4 + 1], bh[p * 4 + 2], bh[p * 4 + 3]);
                ldm_x4(sWlB + d, bl[p * 4 + 0], bl[p * 4 + 1], bl[p * 4 + 2], bl[p * 4 + 3]);
            }
            #pragma unroll
            for (int t = 0; t < 2; t++)
                #pragma unroll
                for (int u = 0; u < 4; u++) {
                    mma16816(acc[t][u], ah[t], &bh[u * 2]);
                    mma16816(acc[t][u], ah[t], &bl[u * 2]);
                    mma16816(acc[t][u], al[t], &bh[u * 2]);
                }
        }
        __syncthreads();
    }

    #pragma unroll
    for (int t = 0; t < 2; t++) {
        const int rbase = m0 + wm * 32 + t * 16 + (lane >> 2);
        #pragma unroll
        for (int u = 0; u < 4; u++) {
            const int gn = n0 + wn * 32 + u * 8 + (lane & 3) * 2;
            const float b0 = __ldg(&bias[gn]);
            const float b1 = __ldg(&bias[gn + 1]);
            #pragma unroll
            for (int h = 0; h < 2; h++) {
                float v0 = acc[t][u][h * 2 + 0] + b0;
                float v1 = acc[t][u][h * 2 + 1] + b1;
                if (relu) { v0 = fmaxf(v0, 0.f); v1 = fmaxf(v1, 0.f); }
                const size_t idx = (size_t)(rbase + h * 8) * ldc + gn;
                if (splitOut) {
                    __nv_bfloat16 h0, l0, h1, l1;
                    split_f32(v0, h0, l0); split_f32(v1, h1, l1);
                    *reinterpret_cast<__nv_bfloat162*>(Ch + idx) = __halves2bfloat162(h0, h1);
                    *reinterpret_cast<__nv_bfloat162*>(Cl + idx) = __halves2bfloat162(l0, l1);
                } else {
                    *reinterpret_cast<float2*>(Cf + idx) = make_float2(v0, v1);
                }
            }
        }
    }
}

// ======== fused gather + interaction (float4 gather, 3x3 tiling) ===========
// Gather: 8 half-warps per block; half-warp hw owns tables hw, hw+8, hw+16,
// hw+24 (<26). Each lane loads one float4 (16B) of the 256B row -> LDG.128.
__global__ void __launch_bounds__(128) gather_interact_kernel(
    const float* __restrict__ x, const float* __restrict__ emb,
    const void* __restrict__ lsi,
    __nv_bfloat16* __restrict__ Rh, __nv_bfloat16* __restrict__ Rl)
{
    __shared__ float s[27][65];
    const int b   = blockIdx.x;
    const int tid = threadIdx.x;
    const int hw  = tid >> 4;       // half-warp 0..7
    const int lh  = tid & 15;       // lane in half-warp
    const int is64 = g_idx_is64;
    const long long* ip64 = (const long long*)lsi;
    const int*       ip32 = (const int*)lsi;

    // x row -> s[0] (16 lanes x float4 = 256B)
    if (tid < 16) {
        float4 v = *reinterpret_cast<const float4*>(x + (size_t)b * 64 + tid * 4);
        s[0][tid * 4 + 0] = v.x; s[0][tid * 4 + 1] = v.y;
        s[0][tid * 4 + 2] = v.z; s[0][tid * 4 + 3] = v.w;
    }

    // embedding gather-sum
    #pragma unroll
    for (int r = 0; r < 4; r++) {
        const int t = hw + r * 8;
        if (t >= NTAB) break;
        const size_t ibase = ((size_t)t * B_SZ + b) * 4;
        const float* tb = emb + (size_t)t * (VOCAB * EMB_D);
        float4 acc = make_float4(0.f, 0.f, 0.f, 0.f);
        #pragma unroll
        for (int l = 0; l < 4; l++) {
            unsigned int ix = is64 ? (unsigned int)ip64[ibase + l]
                                   : (unsigned int)ip32[ibase + l];
            if (ix >= VOCAB) ix = VOCAB - 1;
            const float4* row = reinterpret_cast<const float4*>(tb + (size_t)ix * EMB_D);
            float4 v = __ldg(row + lh);
            acc.x += v.x; acc.y += v.y; acc.z += v.z; acc.w += v.w;
        }
        float* sr = &s[1 + t][lh * 4];
        sr[0] = acc.x; sr[1] = acc.y; sr[2] = acc.z; sr[3] = acc.w;
    }
    __syncthreads();

    __nv_bfloat16* Rbh = Rh + (size_t)b * 448;
    __nv_bfloat16* Rbl = Rl + (size_t)b * 448;

    if (tid < 64) {
        __nv_bfloat16 h, l; split_f32(s[0][tid], h, l);
        Rbh[tid] = h; Rbl[tid] = l;
    }
    for (int c = 415 + tid; c < 448; c += 128) {
        Rbh[c] = __float2bfloat16(0.f); Rbl[c] = __float2bfloat16(0.f);
    }

    // 3x3 tiles: 9 groups of 3 rows; 45 (gi>=gj) tiles
    if (tid < 45) {
        int gi = (int)(0.5f * (sqrtf(8.0f * (float)tid + 1.0f) - 1.0f));
        while (gi * (gi + 1) / 2 > tid) --gi;
        while ((gi + 1) * (gi + 2) / 2 <= tid) ++gi;
        const int gj = tid - gi * (gi + 1) / 2;
        const int i0 = 3 * gi, j0 = 3 * gj;
        const float* si0 = s[i0];
        const float* si1 = s[i0 + 1];
        const float* si2 = s[i0 + 2];
        const float* sj0 = s[j0];
        const float* sj1 = s[j0 + 1];
        const float* sj2 = s[j0 + 2];
        float d[3][3];
        #pragma unroll
        for (int a = 0; a < 3; a++)
            #pragma unroll
            for (int c2 = 0; c2 < 3; c2++) d[a][c2] = 0.f;
        for (int k = 0; k < 64; k++) {
            const float a0 = si0[k], a1 = si1[k], a2 = si2[k];
            const float b0 = sj0[k], b1 = sj1[k], b2 = sj2[k];
            d[0][0] += a0 * b0; d[0][1] += a0 * b1; d[0][2] += a0 * b2;
            d[1][0] += a1 * b0; d[1][1] += a1 * b1; d[1][2] += a1 * b2;
            d[2][0] += a2 * b0; d[2][1] += a2 * b1; d[2][2] += a2 * b2;
        }
        #pragma unroll
        for (int a = 0; a < 3; a++) {
            const int i = i0 + a;
            #pragma unroll
            for (int c2 = 0; c2 < 3; c2++) {
                const int j = j0 + c2;
                if (i > j) {
                    __nv_bfloat16 h, l; split_f32(d[a][c2], h, l);
                    const int p = i * (i - 1) / 2 + j;
                    Rbh[64 + p] = h; Rbl[64 + p] = l;
                }
            }
        }
    }
}

// ======================= final layer + sigmoid ==============================
__global__ void __launch_bounds__(256) top_final_kernel(
    const float* __restrict__ Z, const float* __restrict__ W,
    const float* __restrict__ bias, float* __restrict__ out)
{
    const int b = blockIdx.x * 8 + (threadIdx.x >> 5);
    const int lane = threadIdx.x & 31;
    const float* zr = Z + (size_t)b * 256;
    float acc = 0.f;
    #pragma unroll
    for (int k = lane; k < 256; k += 32) acc += zr[k] * W[k];
    #pragma unroll
    for (int off = 16; off > 0; off >>= 1)
        acc += __shfl_xor_sync(0xFFFFFFFFu, acc, off);
    if (lane == 0) {
        const float v = acc + bias[0];
        out[b] = 1.f / (1.f + expf(-v));
    }
}

// ======================= launch =============================================
extern "C" void kernel_launch(void* const* d_in, const int* in_sizes, int n_in,
                              void* d_out, int out_size)
{
    (void)n_in; (void)out_size;
    const float* dense_x = (const float*)d_in[0];
    const void*  lsi     = d_in[2];
    const float* emb     = (const float*)d_in[3];

    const float *bW0, *bb0, *bW1, *bb1, *bW2, *bb2;
    const float *tW0, *tb0, *tW1, *tb1, *tW2, *tb2;
    if (in_sizes[6] == 512 * 415) {
        bW0 = (const float*)d_in[4];  bb0 = (const float*)d_in[5];
        tW0 = (const float*)d_in[6];  tb0 = (const float*)d_in[7];
        bW1 = (const float*)d_in[8];  bb1 = (const float*)d_in[9];
        tW1 = (const float*)d_in[10]; tb1 = (const float*)d_in[11];
        bW2 = (const float*)d_in[12]; bb2 = (const float*)d_in[13];
        tW2 = (const float*)d_in[14]; tb2 = (const float*)d_in[15];
    } else {
        bW0 = (const float*)d_in[4];  bb0 = (const float*)d_in[5];
        bW1 = (const float*)d_in[6];  bb1 = (const float*)d_in[7];
        bW2 = (const float*)d_in[8];  bb2 = (const float*)d_in[9];
        tW0 = (const float*)d_in[10]; tb0 = (const float*)d_in[11];
        tW1 = (const float*)d_in[12]; tb1 = (const float*)d_in[13];
        tW2 = (const float*)d_in[14]; tb2 = (const float*)d_in[15];
    }

    float *x, *z2;
    __nv_bfloat16 *x1h, *x1l, *x2h, *x2l, *Rh, *Rl, *z1h, *z1l;
    __nv_bfloat16 *bW1h, *bW1l, *bW2h, *bW2l, *tW0h, *tW0l, *tW1h, *tW1l;
    cudaGetSymbolAddress((void**)&x,    g_x);
    cudaGetSymbolAddress((void**)&z2,   g_z2);
    cudaGetSymbolAddress((void**)&x1h,  g_x1h);  cudaGetSymbolAddress((void**)&x1l, g_x1l);
    cudaGetSymbolAddress((void**)&x2h,  g_x2h);  cudaGetSymbolAddress((void**)&x2l, g_x2l);
    cudaGetSymbolAddress((void**)&Rh,   g_Rh);   cudaGetSymbolAddress((void**)&Rl,  g_Rl);
    cudaGetSymbolAddress((void**)&z1h,  g_z1h);  cudaGetSymbolAddress((void**)&z1l, g_z1l);
    cudaGetSymbolAddress((void**)&bW1h, g_bW1h); cudaGetSymbolAddress((void**)&bW1l, g_bW1l);
    cudaGetSymbolAddress((void**)&bW2h, g_bW2h); cudaGetSymbolAddress((void**)&bW2l, g_bW2l);
    cudaGetSymbolAddress((void**)&tW0h, g_tW0h); cudaGetSymbolAddress((void**)&tW0l, g_tW0l);
    cudaGetSymbolAddress((void**)&tW1h, g_tW1h); cudaGetSymbolAddress((void**)&tW1l, g_tW1l);

    const int SMEM = 2 * 49152;   // 96KB -> 2 CTA/SM
    cudaFuncSetAttribute(gemm_mma, cudaFuncAttributeMaxDynamicSharedMemorySize, SMEM);

    // launch 0: fused prep (pad/split + detect) + bot layer 0
    prep_bot0_kernel<<<3009, 256>>>(dense_x, bW0, bb0, x1h, x1l,
                                    bW1, bW2, tW0, tW1, (const int*)lsi,
                                    bW1h, bW1l, bW2h, bW2l,
                                    tW0h, tW0l, tW1h, tW1l);

    // launches 1-2: rest of bottom MLP -> compact x[B,64]
    gemm_mma<<<dim3(4, 128), 256, SMEM>>>(x1h, x1l, bW1h, bW1l, bb1, 512, 8,
                                          nullptr, x2h, x2l, 256, 1, 1);
    gemm_mma<<<dim3(1, 128), 256, SMEM>>>(x2h, x2l, bW2h, bW2l, bb2, 256, 4,
                                          x, nullptr, nullptr, 64, 1, 0);

    // launch 3: fused gather + interaction -> split R[B,448]
    gather_interact_kernel<<<B_SZ, 128>>>(x, emb, lsi, Rh, Rl);

    // launches 4-6: top MLP
    gemm_mma<<<dim3(8, 128), 256, SMEM>>>(Rh, Rl, tW0h, tW0l, tb0, 448, 7,
                                          nullptr, z1h, z1l, 512, 1, 1);
    gemm_mma<<<dim3(4, 128), 256, SMEM>>>(z1h, z1l, tW1h, tW1l, tb1, 512, 8,
                                          z2, nullptr, nullptr, 256, 1, 0);
    top_final_kernel<<<B_SZ / 8, 256>>>(z2, tW2, tb2, (float*)d_out);
}